// round 3
// baseline (speedup 1.0000x reference)
#include <cuda_runtime.h>
#include <cstdint>
#include <cstddef>

#define BB 16
#define NN 8192
#define SS 1024
#define KK 32
#define R2C 0.04f          /* float(0.2**2) as JAX casts the python scalar */
#define EPSC 1e-5f
#define MTOT (BB*SS*KK)    /* 524288 positions */
#define OUT_OFF (BB*SS*3)  /* new_xyz occupies first 49152 floats of d_out */

// ---------------- device scratch (static allocation is the sanctioned path) ---
__device__ int    g_fps[BB*SS];
__device__ int    g_idx[BB*SS*KK];
__device__ float  g_y1[(size_t)MTOT*64];
__device__ float  g_y2[(size_t)MTOT*64];
__device__ float  g_y3[(size_t)MTOT*128];
__device__ double g_sum[3][128];
__device__ double g_sq[3][128];
__device__ float  g_scale[3][128];
__device__ float  g_shift[3][128];

// ---------------- init: zero stat accumulators (graph replays must be clean) --
__global__ void init_kernel() {
    int t = blockIdx.x * blockDim.x + threadIdx.x;
    if (t < 3 * 128) {
        ((double*)g_sum)[t] = 0.0;
        ((double*)g_sq)[t]  = 0.0;
    }
}

// ---------------- farthest point sampling: one CTA per batch -----------------
__global__ __launch_bounds__(1024) void fps_kernel(const float* __restrict__ xyz) {
    int b = blockIdx.x;
    int t = threadIdx.x;
    const float* xb = xyz + (size_t)b * NN * 3;

    float px[8], py[8], pz[8], dist[8];
#pragma unroll
    for (int i = 0; i < 8; i++) {
        int p = t + i * 1024;
        px[i] = xb[p*3+0];
        py[i] = xb[p*3+1];
        pz[i] = xb[p*3+2];
        dist[i] = 1e10f;
    }

    __shared__ float s_val[32];
    __shared__ int   s_idx[32];
    __shared__ int   s_far;
    if (t == 0) s_far = 0;
    __syncthreads();

    for (int it = 0; it < SS; it++) {
        int far = s_far;
        if (t == 0) g_fps[b * SS + it] = far;
        float cx = xb[far*3+0], cy = xb[far*3+1], cz = xb[far*3+2];

        float bestv = -1.0f; int besti = 0;
#pragma unroll
        for (int i = 0; i < 8; i++) {
            float dx = px[i] - cx, dy = py[i] - cy, dz = pz[i] - cz;
            float d = dx*dx + dy*dy + dz*dz;
            float nd = fminf(dist[i], d);
            dist[i] = nd;
            if (nd > bestv) { bestv = nd; besti = t + i * 1024; }
        }
        // warp argmax (ties -> smaller index, matching jnp.argmax)
#pragma unroll
        for (int off = 16; off; off >>= 1) {
            float ov = __shfl_down_sync(0xffffffffu, bestv, off);
            int   oi = __shfl_down_sync(0xffffffffu, besti, off);
            if (ov > bestv || (ov == bestv && oi < besti)) { bestv = ov; besti = oi; }
        }
        if ((t & 31) == 0) { s_val[t >> 5] = bestv; s_idx[t >> 5] = besti; }
        __syncthreads();
        if (t < 32) {
            bestv = s_val[t]; besti = s_idx[t];
#pragma unroll
            for (int off = 16; off; off >>= 1) {
                float ov = __shfl_down_sync(0xffffffffu, bestv, off);
                int   oi = __shfl_down_sync(0xffffffffu, besti, off);
                if (ov > bestv || (ov == bestv && oi < besti)) { bestv = ov; besti = oi; }
            }
            if (t == 0) s_far = besti;
        }
        __syncthreads();
    }
}

// ---------------- gather new_xyz into output ---------------------------------
__global__ void gather_newxyz_kernel(const float* __restrict__ xyz,
                                     float* __restrict__ out) {
    int i = blockIdx.x * blockDim.x + threadIdx.x;
    if (i < BB * SS) {
        int b = i >> 10;
        int j = g_fps[i];
        const float* p = xyz + ((size_t)b * NN + j) * 3;
        out[i*3+0] = p[0];
        out[i*3+1] = p[1];
        out[i*3+2] = p[2];
    }
}

// ---------------- ball query: one warp per query ------------------------------
__global__ void qb_kernel(const float* __restrict__ xyz) {
    int q = (blockIdx.x * blockDim.x + threadIdx.x) >> 5;  // 0..16383
    int lane = threadIdx.x & 31;
    int b = q >> 10;
    const float* xb = xyz + (size_t)b * NN * 3;
    int c = g_fps[q];
    float cx = xb[c*3+0], cy = xb[c*3+1], cz = xb[c*3+2];

    int cnt = 0;
    int first = 0;
    bool have_first = false;
    int* out = g_idx + (size_t)q * KK;

    for (int base = 0; base < NN; base += 32) {
        int p = base + lane;
        float dx = xb[p*3+0] - cx, dy = xb[p*3+1] - cy, dz = xb[p*3+2] - cz;
        float d = dx*dx + dy*dy + dz*dz;
        bool in = (d <= R2C);
        unsigned m = __ballot_sync(0xffffffffu, in);
        if (m) {
            int pos = cnt + __popc(m & ((1u << lane) - 1u));
            if (in && pos < KK) out[pos] = p;
            if (!have_first) { first = base + __ffs(m) - 1; have_first = true; }
            cnt += __popc(m);
            if (cnt >= KK) break;
        }
    }
    for (int pos = cnt + lane; pos < KK; pos += 32) out[pos] = first;
}

// ---------------- layer 1: gather + GEMM (K=67 -> 64) + stats ----------------
// 64 positions per block, 128 threads; thread tile = 4 pos x 8 out.
__global__ __launch_bounds__(128) void layer1_kernel(
    const float* __restrict__ xyz, const float* __restrict__ points,
    const float* __restrict__ newxyz,
    const float* __restrict__ w, const float* __restrict__ bias)
{
    __shared__ __align__(16) float Xs[67][64];
    __shared__ __align__(16) float Ws[67][64];
    __shared__ float sh_b[64], sh_sum[64], sh_sq[64];

    int t = threadIdx.x;
    size_t pos0 = (size_t)blockIdx.x * 64;

    for (int e = t; e < 64 * 67; e += 128) {
        int o = e / 67, c = e % 67;
        Ws[c][o] = w[e];
    }
    if (t < 64) { sh_b[t] = bias[t]; sh_sum[t] = 0.f; sh_sq[t] = 0.f; }

    {   // gather: 2 threads per position
        int p = t >> 1, half = t & 1;
        size_t pos = pos0 + p;
        int j = g_idx[pos];
        int b = (int)(pos >> 15);
        int s = (int)((pos >> 5) & 1023);
        const float4* prow = (const float4*)(points + ((size_t)b * NN + j) * 64) + half * 8;
#pragma unroll
        for (int i = 0; i < 8; i++) {
            float4 v = prow[i];
            int c = 3 + half * 32 + i * 4;
            Xs[c+0][p] = v.x; Xs[c+1][p] = v.y; Xs[c+2][p] = v.z; Xs[c+3][p] = v.w;
        }
        if (!half) {
            const float* xr = xyz + ((size_t)b * NN + j) * 3;
            const float* nr = newxyz + ((size_t)b * SS + s) * 3;
            Xs[0][p] = xr[0] - nr[0];
            Xs[1][p] = xr[1] - nr[1];
            Xs[2][p] = xr[2] - nr[2];
        }
    }
    __syncthreads();

    int px = t >> 3, ox = t & 7;
    float acc[4][8];
#pragma unroll
    for (int i = 0; i < 4; i++)
#pragma unroll
        for (int j = 0; j < 8; j++) acc[i][j] = sh_b[ox*8+j];

#pragma unroll 4
    for (int c = 0; c < 67; c++) {
        float4 xv  = *(const float4*)&Xs[c][px*4];
        float4 w0  = *(const float4*)&Ws[c][ox*8];
        float4 w1v = *(const float4*)&Ws[c][ox*8+4];
        float xa[4] = {xv.x, xv.y, xv.z, xv.w};
        float wa[8] = {w0.x, w0.y, w0.z, w0.w, w1v.x, w1v.y, w1v.z, w1v.w};
#pragma unroll
        for (int i = 0; i < 4; i++)
#pragma unroll
            for (int j = 0; j < 8; j++) acc[i][j] = fmaf(xa[i], wa[j], acc[i][j]);
    }

    float ssum[8], ssq[8];
#pragma unroll
    for (int j = 0; j < 8; j++) { ssum[j] = 0.f; ssq[j] = 0.f; }
#pragma unroll
    for (int i = 0; i < 4; i++) {
        size_t pp = pos0 + px*4 + i;
        *(float4*)&g_y1[pp*64 + ox*8]     = make_float4(acc[i][0], acc[i][1], acc[i][2], acc[i][3]);
        *(float4*)&g_y1[pp*64 + ox*8 + 4] = make_float4(acc[i][4], acc[i][5], acc[i][6], acc[i][7]);
#pragma unroll
        for (int j = 0; j < 8; j++) { ssum[j] += acc[i][j]; ssq[j] += acc[i][j]*acc[i][j]; }
    }
#pragma unroll
    for (int j = 0; j < 8; j++) {
        atomicAdd(&sh_sum[ox*8+j], ssum[j]);
        atomicAdd(&sh_sq[ox*8+j],  ssq[j]);
    }
    __syncthreads();
    if (t < 64) {
        atomicAdd(&g_sum[0][t], (double)sh_sum[t]);
        atomicAdd(&g_sq[0][t],  (double)sh_sq[t]);
    }
}

// ---------------- per-channel BN fold ----------------------------------------
__global__ void stats_kernel(int L, const float* __restrict__ gam,
                             const float* __restrict__ bet, int C) {
    int t = threadIdx.x;
    if (t < C) {
        double mean = g_sum[L][t] * (1.0 / (double)MTOT);
        double var  = g_sq[L][t]  * (1.0 / (double)MTOT) - mean * mean;
        float sc = gam[t] * rsqrtf((float)var + EPSC);
        g_scale[L][t] = sc;
        g_shift[L][t] = fmaf(-(float)mean, sc, bet[t]);
    }
}

// ---------------- layers 2/3: affine+relu(in) -> GEMM -> stats ---------------
// L=2: g_y1 -> g_y2 (64x64). L=3: g_y2 -> g_y3 (64x128).
template<int L, int NO, int POSB, int PX, int OX>
__global__ void layer_kernel(const float* __restrict__ w,
                             const float* __restrict__ bias)
{
    constexpr int THREADS = PX * OX;
    constexpr int TP = POSB / PX;           // 4
    constexpr int TO = NO / OX;             // 8 or 4
    constexpr int TPP = THREADS / POSB;     // threads per position
    constexpr int V4 = 16 / TPP;            // float4s per thread on load
    static_assert(TP == 4, "TP must be 4");

    const float* xin = (L == 2) ? g_y1 : g_y2;
    float*       y   = (L == 2) ? g_y2 : g_y3;

    __shared__ __align__(16) float Xs[64][POSB];
    __shared__ __align__(16) float Ws[64][NO];
    __shared__ float sh_b[NO], sh_sum[NO], sh_sq[NO];
    __shared__ float sh_scale[64], sh_shift[64];

    int t = threadIdx.x;
    size_t pos0 = (size_t)blockIdx.x * POSB;

    for (int e = t; e < NO * 64; e += THREADS) {
        int o = e >> 6, c = e & 63;
        Ws[c][o] = w[e];
    }
    if (t < NO) { sh_b[t] = bias[t]; sh_sum[t] = 0.f; sh_sq[t] = 0.f; }
    if (t < 64) { sh_scale[t] = g_scale[L-2][t]; sh_shift[t] = g_shift[L-2][t]; }
    __syncthreads();

    {   // staged input load with fused affine+relu
        int p = t / TPP, sub = t % TPP;
        const float4* row = (const float4*)(xin + (pos0 + p) * 64) + sub * V4;
#pragma unroll
        for (int i = 0; i < V4; i++) {
            float4 v = row[i];
            int c = (sub * V4 + i) * 4;
            Xs[c+0][p] = fmaxf(fmaf(v.x, sh_scale[c+0], sh_shift[c+0]), 0.f);
            Xs[c+1][p] = fmaxf(fmaf(v.y, sh_scale[c+1], sh_shift[c+1]), 0.f);
            Xs[c+2][p] = fmaxf(fmaf(v.z, sh_scale[c+2], sh_shift[c+2]), 0.f);
            Xs[c+3][p] = fmaxf(fmaf(v.w, sh_scale[c+3], sh_shift[c+3]), 0.f);
        }
    }
    __syncthreads();

    int px = t / OX, ox = t % OX;
    float acc[TP][TO];
#pragma unroll
    for (int i = 0; i < TP; i++)
#pragma unroll
        for (int j = 0; j < TO; j++) acc[i][j] = sh_b[ox*TO+j];

#pragma unroll 4
    for (int c = 0; c < 64; c++) {
        float4 xv = *(const float4*)&Xs[c][px*TP];
        float xa[4] = {xv.x, xv.y, xv.z, xv.w};
        float wa[TO];
#pragma unroll
        for (int j = 0; j < TO; j += 4) {
            float4 wv = *(const float4*)&Ws[c][ox*TO + j];
            wa[j] = wv.x; wa[j+1] = wv.y; wa[j+2] = wv.z; wa[j+3] = wv.w;
        }
#pragma unroll
        for (int i = 0; i < TP; i++)
#pragma unroll
            for (int j = 0; j < TO; j++) acc[i][j] = fmaf(xa[i], wa[j], acc[i][j]);
    }

    float ssum[TO], ssq[TO];
#pragma unroll
    for (int j = 0; j < TO; j++) { ssum[j] = 0.f; ssq[j] = 0.f; }
#pragma unroll
    for (int i = 0; i < TP; i++) {
        size_t pp = pos0 + px*TP + i;
#pragma unroll
        for (int j = 0; j < TO; j += 4) {
            *(float4*)&y[pp*NO + ox*TO + j] =
                make_float4(acc[i][j], acc[i][j+1], acc[i][j+2], acc[i][j+3]);
        }
#pragma unroll
        for (int j = 0; j < TO; j++) { ssum[j] += acc[i][j]; ssq[j] += acc[i][j]*acc[i][j]; }
    }
#pragma unroll
    for (int j = 0; j < TO; j++) {
        atomicAdd(&sh_sum[ox*TO+j], ssum[j]);
        atomicAdd(&sh_sq[ox*TO+j],  ssq[j]);
    }
    __syncthreads();
    if (t < NO) {
        atomicAdd(&g_sum[L-1][t], (double)sh_sum[t]);
        atomicAdd(&g_sq[L-1][t],  (double)sh_sq[t]);
    }
}

// ---------------- final: affine+relu + max over nsample + transpose ----------
__global__ void final_kernel(float* __restrict__ out) {
    int q = blockIdx.x;          // (b,s) 0..16383
    int o = threadIdx.x;         // channel 0..127
    float sc = g_scale[2][o], sh = g_shift[2][o];
    const float* base = g_y3 + (size_t)q * KK * 128;
    float m = 0.0f;  // relu output >= 0 and KK >= 1
#pragma unroll 8
    for (int k = 0; k < KK; k++) {
        float v = fmaxf(fmaf(base[k*128 + o], sc, sh), 0.f);
        m = fmaxf(m, v);
    }
    int b = q >> 10, s = q & 1023;
    out[OUT_OFF + ((size_t)b * 128 + o) * SS + s] = m;
}

// ---------------- launcher ----------------------------------------------------
extern "C" void kernel_launch(void* const* d_in, const int* in_sizes, int n_in,
                              void* d_out, int out_size) {
    (void)in_sizes; (void)n_in; (void)out_size;
    const float* xyz    = (const float*)d_in[0];
    const float* points = (const float*)d_in[1];
    const float* w1  = (const float*)d_in[2];
    const float* b1  = (const float*)d_in[3];
    const float* g1  = (const float*)d_in[4];
    const float* be1 = (const float*)d_in[5];
    const float* w2  = (const float*)d_in[6];
    const float* b2  = (const float*)d_in[7];
    const float* g2  = (const float*)d_in[8];
    const float* be2 = (const float*)d_in[9];
    const float* w3  = (const float*)d_in[10];
    const float* b3  = (const float*)d_in[11];
    const float* g3  = (const float*)d_in[12];
    const float* be3 = (const float*)d_in[13];
    float* out = (float*)d_out;

    init_kernel<<<1, 512>>>();
    fps_kernel<<<BB, 1024>>>(xyz);
    gather_newxyz_kernel<<<(BB*SS + 255) / 256, 256>>>(xyz, out);
    qb_kernel<<<(BB*SS) / 8, 256>>>(xyz);

    layer1_kernel<<<MTOT / 64, 128>>>(xyz, points, out, w1, b1);
    stats_kernel<<<1, 128>>>(0, g1, be1, 64);

    layer_kernel<2, 64, 64, 16, 8><<<MTOT / 64, 128>>>(w2, b2);
    stats_kernel<<<1, 128>>>(1, g2, be2, 64);

    layer_kernel<3, 128, 32, 8, 32><<<MTOT / 32, 256>>>(w3, b3);
    stats_kernel<<<1, 128>>>(2, g3, be3, 128);

    final_kernel<<<BB * SS, 128>>>(out);
}